// round 16
// baseline (speedup 1.0000x reference)
#include <cuda_runtime.h>

// CCC loss: B=512 rows, T=65536 cols, fp32.  FINAL — converged (held).
// Distribution over 7 identical-source runs: {43.5, 45.3, 45.2, 43.5, 45.1,
// 45.3, 45.2} us total (main 43.1-44.9); floor 43.5 reproduced twice; best
// main 43.1 us @ 6.32 TB/s = the path-independent ~6.3 TB/s LTS chip cap
// (arithmetic floor 40.6 us + ramp/tail; beats the T_chip spread-floor
// estimate of 44.7 us). Variance = NAT-clock DVFS over byte-identical SASS.
// Total-main gap ~1.4 us = harness launch fixed cost (single launch).
//
// Structure: one CTA per row (512 x 512 threads). Inner loop batches 4
// independent LDG.128 (two iterations x two inputs) before any FMA consumes
// them; 32 regs/thread = exact one-wave RF budget (4 CTAs/SM, all 512 CTAs
// resident in a single wave). Single fused kernel: last-arriving CTA
// (threadfence-reduction) computes per-row CCC and the mean, then resets
// the counter so every CUDA-graph replay is deterministic.
//
// Levers swept & measured: fusion (WIN +2.1us), 2-deep LDG batch (WIN
// +1.3us), 2048x256 grid (LOSS), __ldcs (LOSS), 4-deep batch (NEUTRAL,
// ptxas reclamps), SoA partials (NEUTRAL). Model-rejected as neutral:
// 1024-thread CTAs (2-wave), TMA/cp.async (LTS cap path-independent),
// address staggering (die hash ~Bernoulli @2KB), deeper MLP (covered 4x).

#define B 512
#define T 65536
#define THREADS 512
#define EPS 1e-8f

__device__ float g_partials[B * 5];
__device__ unsigned int g_count;  // zero-init; reset by last block

__device__ __forceinline__ float warp_sum(float v) {
    #pragma unroll
    for (int o = 16; o > 0; o >>= 1)
        v += __shfl_down_sync(0xFFFFFFFFu, v, o);
    return v;
}

__global__ __launch_bounds__(THREADS)
void ccc_fused(const float* __restrict__ preds,
               const float* __restrict__ labels,
               float* __restrict__ out) {
    const int row  = blockIdx.x;
    const int tid  = threadIdx.x;
    const int lane = tid & 31;
    const int wid  = tid >> 5;

    const float4* __restrict__ px =
        reinterpret_cast<const float4*>(preds  + (size_t)row * T);
    const float4* __restrict__ py =
        reinterpret_cast<const float4*>(labels + (size_t)row * T);

    float sx = 0.f, sy = 0.f, sxx = 0.f, syy = 0.f, sxy = 0.f;

    // 16384 float4 per row, 512 threads -> 32 iterations, processed 2 at a
    // time with all 4 loads issued before any consumption.
    #pragma unroll 2
    for (int j = 0; j < 32; j += 2) {
        const int iA = tid + j * THREADS;
        const int iB = iA + THREADS;
        float4 xa = px[iA];
        float4 ya = py[iA];
        float4 xb = px[iB];
        float4 yb = py[iB];

        sx  += xa.x + xa.y + xa.z + xa.w;
        sy  += ya.x + ya.y + ya.z + ya.w;
        sxx += xa.x * xa.x + xa.y * xa.y + xa.z * xa.z + xa.w * xa.w;
        syy += ya.x * ya.x + ya.y * ya.y + ya.z * ya.z + ya.w * ya.w;
        sxy += xa.x * ya.x + xa.y * ya.y + xa.z * ya.z + xa.w * ya.w;

        sx  += xb.x + xb.y + xb.z + xb.w;
        sy  += yb.x + yb.y + yb.z + yb.w;
        sxx += xb.x * xb.x + xb.y * xb.y + xb.z * xb.z + xb.w * xb.w;
        syy += yb.x * yb.x + yb.y * yb.y + yb.z * yb.z + yb.w * yb.w;
        sxy += xb.x * yb.x + xb.y * yb.y + xb.z * yb.z + xb.w * yb.w;
    }

    sx  = warp_sum(sx);
    sy  = warp_sum(sy);
    sxx = warp_sum(sxx);
    syy = warp_sum(syy);
    sxy = warp_sum(sxy);

    __shared__ float s[5][THREADS / 32];
    if (lane == 0) {
        s[0][wid] = sx;  s[1][wid] = sy;  s[2][wid] = sxx;
        s[3][wid] = syy; s[4][wid] = sxy;
    }
    __syncthreads();

    if (wid == 0) {
        const unsigned nW = THREADS / 32;  // 16
        float v0 = (lane < nW) ? s[0][lane] : 0.f;
        float v1 = (lane < nW) ? s[1][lane] : 0.f;
        float v2 = (lane < nW) ? s[2][lane] : 0.f;
        float v3 = (lane < nW) ? s[3][lane] : 0.f;
        float v4 = (lane < nW) ? s[4][lane] : 0.f;
        v0 = warp_sum(v0); v1 = warp_sum(v1); v2 = warp_sum(v2);
        v3 = warp_sum(v3); v4 = warp_sum(v4);
        if (lane == 0) {
            g_partials[row * 5 + 0] = v0;
            g_partials[row * 5 + 1] = v1;
            g_partials[row * 5 + 2] = v2;
            g_partials[row * 5 + 3] = v3;
            g_partials[row * 5 + 4] = v4;
        }
    }

    // ---- last-block finalize ----
    __shared__ bool isLast;
    if (tid == 0) {
        __threadfence();
        unsigned c = atomicAdd(&g_count, 1u);
        isLast = (c == (unsigned)gridDim.x - 1u);
    }
    __syncthreads();

    if (isLast) {
        const float invT = 1.0f / (float)T;
        // one thread per row (tid = 0..511)
        float fsx  = g_partials[tid * 5 + 0];
        float fsy  = g_partials[tid * 5 + 1];
        float fsxx = g_partials[tid * 5 + 2];
        float fsyy = g_partials[tid * 5 + 3];
        float fsxy = g_partials[tid * 5 + 4];

        float mx = fsx * invT;
        float my = fsy * invT;
        float var_x = fsxx * invT - mx * mx;
        float var_y = fsyy * invT - my * my;
        float cov   = fsxy * invT - mx * my;
        float dm = mx - my;
        float loss = 1.0f - 2.0f * cov / (var_x + var_y + dm * dm + EPS);

        loss = warp_sum(loss);
        __shared__ float sf[THREADS / 32];
        if (lane == 0) sf[wid] = loss;
        __syncthreads();
        if (wid == 0) {
            float v = (lane < THREADS / 32) ? sf[lane] : 0.f;
            v = warp_sum(v);
            if (lane == 0) {
                out[0] = v / (float)B;
                g_count = 0;  // reset for next graph replay
            }
        }
    }
}

extern "C" void kernel_launch(void* const* d_in, const int* in_sizes, int n_in,
                              void* d_out, int out_size) {
    const float* preds  = (const float*)d_in[0];
    const float* labels = (const float*)d_in[1];
    float* out = (float*)d_out;

    ccc_fused<<<B, THREADS>>>(preds, labels, out);
}

// round 17
// speedup vs baseline: 1.0449x; 1.0449x over previous
#include <cuda_runtime.h>

// CCC loss: B=512 rows, T=65536 cols, fp32.  FINAL — converged (held).
// Distribution over 8 identical-source runs: {43.5, 45.3, 45.2, 43.5, 45.1,
// 45.3, 45.2, 45.4} us total (main 43.1-44.9); floor 43.5 reproduced twice;
// best main 43.1 us @ 6.32 TB/s = the path-independent ~6.3 TB/s LTS chip
// cap (arithmetic floor 40.6 us + ramp/tail). Variance = NAT-clock DVFS
// over byte-identical SASS (regs 32, occ 81-86%, issue ~17% on every run).
//
// Structure: one CTA per row (512 x 512 threads). Inner loop batches 4
// independent LDG.128 (two iterations x two inputs) before any FMA consumes
// them; 32 regs/thread = exact one-wave RF budget (4 CTAs/SM, all 512 CTAs
// resident in a single wave). Single fused kernel: last-arriving CTA
// (threadfence-reduction) computes per-row CCC and the mean, then resets
// the counter so every CUDA-graph replay is deterministic.
//
// Session ledger (45.8 -> 43.5 us floor):
//   fusion of finalize        -> WIN  (+2.1 us, predicted)
//   explicit 2-deep LDG batch -> WIN  (+1.3 us, DRAM 76.6->79.8%, predicted)
//   CTA granularity 2048x256  -> LOSS (reverted)
//   __ldcs streaming hints    -> LOSS (reverted, regs 32->40)
//   4-deep LDG batch          -> NEUTRAL (ptxas reclamps to 32 regs)
//   SoA partials              -> NEUTRAL
//   model-rejected: TMA/cp.async (LTS cap path-independent), 1024-thread
//   CTAs, address staggering, deeper MLP (latency covered 4x).

#define B 512
#define T 65536
#define THREADS 512
#define EPS 1e-8f

__device__ float g_partials[B * 5];
__device__ unsigned int g_count;  // zero-init; reset by last block

__device__ __forceinline__ float warp_sum(float v) {
    #pragma unroll
    for (int o = 16; o > 0; o >>= 1)
        v += __shfl_down_sync(0xFFFFFFFFu, v, o);
    return v;
}

__global__ __launch_bounds__(THREADS)
void ccc_fused(const float* __restrict__ preds,
               const float* __restrict__ labels,
               float* __restrict__ out) {
    const int row  = blockIdx.x;
    const int tid  = threadIdx.x;
    const int lane = tid & 31;
    const int wid  = tid >> 5;

    const float4* __restrict__ px =
        reinterpret_cast<const float4*>(preds  + (size_t)row * T);
    const float4* __restrict__ py =
        reinterpret_cast<const float4*>(labels + (size_t)row * T);

    float sx = 0.f, sy = 0.f, sxx = 0.f, syy = 0.f, sxy = 0.f;

    // 16384 float4 per row, 512 threads -> 32 iterations, processed 2 at a
    // time with all 4 loads issued before any consumption.
    #pragma unroll 2
    for (int j = 0; j < 32; j += 2) {
        const int iA = tid + j * THREADS;
        const int iB = iA + THREADS;
        float4 xa = px[iA];
        float4 ya = py[iA];
        float4 xb = px[iB];
        float4 yb = py[iB];

        sx  += xa.x + xa.y + xa.z + xa.w;
        sy  += ya.x + ya.y + ya.z + ya.w;
        sxx += xa.x * xa.x + xa.y * xa.y + xa.z * xa.z + xa.w * xa.w;
        syy += ya.x * ya.x + ya.y * ya.y + ya.z * ya.z + ya.w * ya.w;
        sxy += xa.x * ya.x + xa.y * ya.y + xa.z * ya.z + xa.w * ya.w;

        sx  += xb.x + xb.y + xb.z + xb.w;
        sy  += yb.x + yb.y + yb.z + yb.w;
        sxx += xb.x * xb.x + xb.y * xb.y + xb.z * xb.z + xb.w * xb.w;
        syy += yb.x * yb.x + yb.y * yb.y + yb.z * yb.z + yb.w * yb.w;
        sxy += xb.x * yb.x + xb.y * yb.y + xb.z * yb.z + xb.w * yb.w;
    }

    sx  = warp_sum(sx);
    sy  = warp_sum(sy);
    sxx = warp_sum(sxx);
    syy = warp_sum(syy);
    sxy = warp_sum(sxy);

    __shared__ float s[5][THREADS / 32];
    if (lane == 0) {
        s[0][wid] = sx;  s[1][wid] = sy;  s[2][wid] = sxx;
        s[3][wid] = syy; s[4][wid] = sxy;
    }
    __syncthreads();

    if (wid == 0) {
        const unsigned nW = THREADS / 32;  // 16
        float v0 = (lane < nW) ? s[0][lane] : 0.f;
        float v1 = (lane < nW) ? s[1][lane] : 0.f;
        float v2 = (lane < nW) ? s[2][lane] : 0.f;
        float v3 = (lane < nW) ? s[3][lane] : 0.f;
        float v4 = (lane < nW) ? s[4][lane] : 0.f;
        v0 = warp_sum(v0); v1 = warp_sum(v1); v2 = warp_sum(v2);
        v3 = warp_sum(v3); v4 = warp_sum(v4);
        if (lane == 0) {
            g_partials[row * 5 + 0] = v0;
            g_partials[row * 5 + 1] = v1;
            g_partials[row * 5 + 2] = v2;
            g_partials[row * 5 + 3] = v3;
            g_partials[row * 5 + 4] = v4;
        }
    }

    // ---- last-block finalize ----
    __shared__ bool isLast;
    if (tid == 0) {
        __threadfence();
        unsigned c = atomicAdd(&g_count, 1u);
        isLast = (c == (unsigned)gridDim.x - 1u);
    }
    __syncthreads();

    if (isLast) {
        const float invT = 1.0f / (float)T;
        // one thread per row (tid = 0..511)
        float fsx  = g_partials[tid * 5 + 0];
        float fsy  = g_partials[tid * 5 + 1];
        float fsxx = g_partials[tid * 5 + 2];
        float fsyy = g_partials[tid * 5 + 3];
        float fsxy = g_partials[tid * 5 + 4];

        float mx = fsx * invT;
        float my = fsy * invT;
        float var_x = fsxx * invT - mx * mx;
        float var_y = fsyy * invT - my * my;
        float cov   = fsxy * invT - mx * my;
        float dm = mx - my;
        float loss = 1.0f - 2.0f * cov / (var_x + var_y + dm * dm + EPS);

        loss = warp_sum(loss);
        __shared__ float sf[THREADS / 32];
        if (lane == 0) sf[wid] = loss;
        __syncthreads();
        if (wid == 0) {
            float v = (lane < THREADS / 32) ? sf[lane] : 0.f;
            v = warp_sum(v);
            if (lane == 0) {
                out[0] = v / (float)B;
                g_count = 0;  // reset for next graph replay
            }
        }
    }
}

extern "C" void kernel_launch(void* const* d_in, const int* in_sizes, int n_in,
                              void* d_out, int out_size) {
    const float* preds  = (const float*)d_in[0];
    const float* labels = (const float*)d_in[1];
    float* out = (float*)d_out;

    ccc_fused<<<B, THREADS>>>(preds, labels, out);
}